// round 4
// baseline (speedup 1.0000x reference)
#include <cuda_runtime.h>
#include <math.h>

#define NNODES 50000
#define NEDGES 600000
#define DD 128
#define NGRAPHS 512
#define NCLASSES 10
#define NLAYERS 4

// ---------------- scratch (static device globals; referenced directly) ------
__device__ float d_h[NNODES * DD];
__device__ float d_m[NNODES * DD];
__device__ float d_agg[NNODES * DD];
__device__ float d_gi[NNODES * 3 * DD];
__device__ float d_gh[NNODES * 3 * DD];
__device__ int   d_off[NNODES + 1];
__device__ int   d_cnt[NNODES];
__device__ int   d_csc[NEDGES];
__device__ float d_pool[NGRAPHS * DD];
__device__ float d_gcnt[NGRAPHS];
__device__ float d_logits[NGRAPHS * NCLASSES];
__device__ int   d_is64;   // 1 if index tensors are int64, 0 if int32

// ---------------- index dtype detection -------------------------------------
// Node ids < 50000 < 2^31, so int64 data has every odd 32-bit word == 0.
// int32 data has random node ids in odd words (P(all 128 zero) ~ 0).
__global__ void detect_kernel(const void* __restrict__ ei) {
    __shared__ int nz;
    if (threadIdx.x == 0) nz = 0;
    __syncthreads();
    const int* w = (const int*)ei;
    int v = w[2 * threadIdx.x + 1];  // odd words 1,3,...,255 (well within buffer)
    if (v != 0) atomicAdd(&nz, 1);
    __syncthreads();
    if (threadIdx.x == 0) d_is64 = (nz == 0) ? 1 : 0;
}

__device__ __forceinline__ int load_idx(const void* p, int i) {
    return d_is64 ? (int)((const long long*)p)[i] : ((const int*)p)[i];
}

// ---------------- small utility kernels ------------------------------------
__global__ void copy_h_kernel(const float* __restrict__ src, int n) {
    int i = blockIdx.x * blockDim.x + threadIdx.x;
    if (i < n) d_h[i] = src[i];
}

__global__ void zero_cnt_kernel(int n) {
    int i = blockIdx.x * blockDim.x + threadIdx.x;
    if (i < n) d_cnt[i] = 0;
}

__global__ void zero_pool_kernel() {
    int i = blockIdx.x * blockDim.x + threadIdx.x;
    if (i < NGRAPHS * DD) d_pool[i] = 0.f;
    if (i < NGRAPHS) d_gcnt[i] = 0.f;
}

// ---------------- CSC build -------------------------------------------------
__global__ void count_kernel(const void* __restrict__ ei, int n_edges) {
    int e = blockIdx.x * blockDim.x + threadIdx.x;
    if (e >= n_edges) return;
    int dst = load_idx(ei, n_edges + e);
    if (dst >= 0 && dst < NNODES) atomicAdd(&d_cnt[dst], 1);
}

// single-block exclusive scan over n elements; d_off[n] = total
__global__ void scan_kernel(int n) {
    __shared__ int tmp[1024];
    __shared__ int carry;
    int tid = threadIdx.x;
    if (tid == 0) carry = 0;
    __syncthreads();
    for (int base = 0; base < n; base += 1024) {
        int v = (base + tid < n) ? d_cnt[base + tid] : 0;
        tmp[tid] = v;
        __syncthreads();
        for (int off = 1; off < 1024; off <<= 1) {
            int t = (tid >= off) ? tmp[tid - off] : 0;
            __syncthreads();
            tmp[tid] += t;
            __syncthreads();
        }
        int excl = tmp[tid] - v;
        if (base + tid < n) d_off[base + tid] = carry + excl;
        __syncthreads();
        if (tid == 1023) carry += tmp[1023];
        __syncthreads();
    }
    if (tid == 0) d_off[n] = carry;
}

__global__ void fill_kernel(const void* __restrict__ ei, int n_edges) {
    int e = blockIdx.x * blockDim.x + threadIdx.x;
    if (e >= n_edges) return;
    int dst = load_idx(ei, n_edges + e);
    int src = load_idx(ei, e);
    if (dst < 0 || dst >= NNODES || src < 0 || src >= NNODES) return;
    int pos = d_off[dst] + atomicAdd(&d_cnt[dst], 1);
    if (pos < NEDGES) d_csc[pos] = src;
}

// ---------------- aggregation: one warp per node, float4 per lane -----------
__global__ void agg_kernel(int n_nodes) {
    int warp = (blockIdx.x * blockDim.x + threadIdx.x) >> 5;
    int lane = threadIdx.x & 31;
    if (warp >= n_nodes) return;
    int s = d_off[warp], e = d_off[warp + 1];
    float4 acc = make_float4(0.f, 0.f, 0.f, 0.f);
    for (int i = s; i < e; i++) {
        int src = d_csc[i];
        float4 v = *(const float4*)(d_m + (size_t)src * DD + lane * 4);
        acc.x += v.x; acc.y += v.y; acc.z += v.z; acc.w += v.w;
    }
    *(float4*)(d_agg + (size_t)warp * DD + lane * 4) = acc;
}

// ---------------- register-tiled fp32 GEMM body ------------------------------
// C[M,N] = A[M,128] * op(B) (+ bias[N]); op(B)=B[K,N] (tb=false) or B[N,K]^T (tb=true)
template <bool TB>
__device__ __forceinline__ void gemm_body(const float* __restrict__ A,
                                          const float* __restrict__ B,
                                          const float* __restrict__ bias,
                                          float* __restrict__ C, int M, int N) {
    const int K = 128;
    const int BM = 128, BN = 64, BK = 16;
    __shared__ float sA[BK][BM + 4];
    __shared__ float sB[BK][BN + 4];

    int m0 = blockIdx.x * BM;
    int n0 = blockIdx.y * BN;
    int tid = threadIdx.x;
    int tr = tid >> 4;   // 0..15
    int tc = tid & 15;   // 0..15

    float acc[8][4];
#pragma unroll
    for (int i = 0; i < 8; i++)
#pragma unroll
        for (int j = 0; j < 4; j++) acc[i][j] = 0.f;

    for (int k0 = 0; k0 < K; k0 += BK) {
#pragma unroll
        for (int t = 0; t < 2; t++) {
            int idx = tid + t * 256;
            int row = idx >> 2;
            int kq = idx & 3;
            float4 v = make_float4(0.f, 0.f, 0.f, 0.f);
            int gr = m0 + row;
            if (gr < M) v = *(const float4*)(A + (size_t)gr * K + k0 + kq * 4);
            sA[kq * 4 + 0][row] = v.x;
            sA[kq * 4 + 1][row] = v.y;
            sA[kq * 4 + 2][row] = v.z;
            sA[kq * 4 + 3][row] = v.w;
        }
        if (TB) {
            int j = tid >> 2;
            int kq = tid & 3;
            float4 v = *(const float4*)(B + (size_t)(n0 + j) * K + k0 + kq * 4);
            sB[kq * 4 + 0][j] = v.x;
            sB[kq * 4 + 1][j] = v.y;
            sB[kq * 4 + 2][j] = v.z;
            sB[kq * 4 + 3][j] = v.w;
        } else {
            int kk = tid >> 4;
            int nq = tid & 15;
            float4 v = *(const float4*)(B + (size_t)(k0 + kk) * N + n0 + nq * 4);
            *(float4*)&sB[kk][nq * 4] = v;
        }
        __syncthreads();

#pragma unroll
        for (int kk = 0; kk < BK; kk++) {
            float a[8], b[4];
#pragma unroll
            for (int i = 0; i < 8; i++) a[i] = sA[kk][tr * 8 + i];
#pragma unroll
            for (int j = 0; j < 4; j++) b[j] = sB[kk][tc * 4 + j];
#pragma unroll
            for (int i = 0; i < 8; i++)
#pragma unroll
                for (int j = 0; j < 4; j++) acc[i][j] += a[i] * b[j];
        }
        __syncthreads();
    }

#pragma unroll
    for (int i = 0; i < 8; i++) {
        int gr = m0 + tr * 8 + i;
        if (gr < M) {
#pragma unroll
            for (int j = 0; j < 4; j++) {
                int gc = n0 + tc * 4 + j;
                float v = acc[i][j];
                if (bias) v += bias[gc];
                C[(size_t)gr * N + gc] = v;
            }
        }
    }
}

// wrappers binding the device-global scratch buffers
__global__ __launch_bounds__(256) void gemm_hWs(const float* __restrict__ B, int M) {
    gemm_body<false>(d_h, B, nullptr, d_m, M, DD);
}
__global__ __launch_bounds__(256) void gemm_aggWih(const float* __restrict__ B,
                                                   const float* __restrict__ bias, int M) {
    gemm_body<true>(d_agg, B, bias, d_gi, M, 3 * DD);
}
__global__ __launch_bounds__(256) void gemm_hWhh(const float* __restrict__ B,
                                                 const float* __restrict__ bias, int M) {
    gemm_body<true>(d_h, B, bias, d_gh, M, 3 * DD);
}

// ---------------- fused GRU gates + ReLU ------------------------------------
__global__ void gru_kernel(int n_nodes) {
    int idx = blockIdx.x * blockDim.x + threadIdx.x;
    if (idx >= n_nodes * DD) return;
    int i = idx / DD, j = idx % DD;
    const float* gir = d_gi + (size_t)i * 3 * DD;
    const float* ghr = d_gh + (size_t)i * 3 * DD;
    float ir = gir[j], iz = gir[DD + j], in_ = gir[2 * DD + j];
    float hr = ghr[j], hz = ghr[DD + j], hn = ghr[2 * DD + j];
    float r = 1.f / (1.f + expf(-(ir + hr)));
    float z = 1.f / (1.f + expf(-(iz + hz)));
    float nn = tanhf(in_ + r * hn);
    float hv = d_h[idx];
    float out = (1.f - z) * nn + z * hv;
    d_h[idx] = fmaxf(out, 0.f);
}

// ---------------- mean pool -------------------------------------------------
__global__ void pool_kernel(const void* __restrict__ batch, int n_nodes) {
    int idx = blockIdx.x * blockDim.x + threadIdx.x;
    if (idx >= n_nodes * DD) return;
    int i = idx / DD, j = idx % DD;
    int g = load_idx(batch, i);
    if (g < 0 || g >= NGRAPHS) return;
    atomicAdd(&d_pool[g * DD + j], d_h[idx]);
    if (j == 0) atomicAdd(&d_gcnt[g], 1.f);
}

// ---------------- readout FC1(elu) + FC2 ------------------------------------
__global__ void readout_kernel(const float* __restrict__ fc1w, const float* __restrict__ fc1b,
                               const float* __restrict__ fc2w, const float* __restrict__ fc2b) {
    int g = blockIdx.x;
    int j = threadIdx.x;  // 128
    __shared__ float hg[DD];
    __shared__ float h2[DD];
    float c = fmaxf(d_gcnt[g], 1.f);
    hg[j] = d_pool[g * DD + j] / c;
    __syncthreads();
    float a = fc1b[j];
#pragma unroll 4
    for (int k = 0; k < DD; k++) a += hg[k] * fc1w[j * DD + k];
    h2[j] = (a > 0.f) ? a : expm1f(a);
    __syncthreads();
    if (j < NCLASSES) {
        float s = fc2b[j];
#pragma unroll 4
        for (int k = 0; k < DD; k++) s += h2[k] * fc2w[j * DD + k];
        d_logits[g * NCLASSES + j] = s;
    }
}

// ---------------- log_softmax over axis 0 (graphs) --------------------------
__global__ void lsm_kernel(float* __restrict__ out) {
    int c = blockIdx.x;   // class
    int g = threadIdx.x;  // 512 graphs
    __shared__ float sh[NGRAPHS];
    float x = d_logits[g * NCLASSES + c];
    sh[g] = x;
    __syncthreads();
    for (int off = NGRAPHS / 2; off > 0; off >>= 1) {
        if (g < off) sh[g] = fmaxf(sh[g], sh[g + off]);
        __syncthreads();
    }
    float mx = sh[0];
    __syncthreads();
    sh[g] = expf(x - mx);
    __syncthreads();
    for (int off = NGRAPHS / 2; off > 0; off >>= 1) {
        if (g < off) sh[g] += sh[g + off];
        __syncthreads();
    }
    float lse = mx + logf(sh[0]);
    out[g * NCLASSES + c] = x - lse;
}

// ---------------- launch ----------------------------------------------------
extern "C" void kernel_launch(void* const* d_in, const int* in_sizes, int n_in,
                              void* d_out, int out_size) {
    const float* h_in  = (const float*)d_in[0];
    const void*  ei    = d_in[1];
    // d_in[2] edge_attr: unused by reference
    const void*  batch = d_in[3];
    const float* Ws   = (const float*)d_in[4];
    const float* Wih  = (const float*)d_in[5];
    const float* Whh  = (const float*)d_in[6];
    const float* bih  = (const float*)d_in[7];
    const float* bhh  = (const float*)d_in[8];
    const float* fc1w = (const float*)d_in[9];
    const float* fc1b = (const float*)d_in[10];
    const float* fc2w = (const float*)d_in[11];
    const float* fc2b = (const float*)d_in[12];
    float* out = (float*)d_out;

    int n_nodes = in_sizes[0] / DD;
    int n_edges = in_sizes[1] / 2;
    int nh = n_nodes * DD;

    detect_kernel<<<1, 128>>>(ei);
    copy_h_kernel<<<(nh + 255) / 256, 256>>>(h_in, nh);

    // CSC build (once; reused across all 4 layers)
    zero_cnt_kernel<<<(n_nodes + 255) / 256, 256>>>(n_nodes);
    count_kernel<<<(n_edges + 255) / 256, 256>>>(ei, n_edges);
    scan_kernel<<<1, 1024>>>(n_nodes);
    zero_cnt_kernel<<<(n_nodes + 255) / 256, 256>>>(n_nodes);
    fill_kernel<<<(n_edges + 255) / 256, 256>>>(ei, n_edges);

    dim3 g1((n_nodes + 127) / 128, DD / 64);
    dim3 g3((n_nodes + 127) / 128, (3 * DD) / 64);

    for (int l = 0; l < NLAYERS; l++) {
        gemm_hWs<<<g1, 256>>>(Ws + (size_t)l * DD * DD, n_nodes);
        agg_kernel<<<(n_nodes * 32 + 255) / 256, 256>>>(n_nodes);
        gemm_aggWih<<<g3, 256>>>(Wih + (size_t)l * 3 * DD * DD, bih + (size_t)l * 3 * DD, n_nodes);
        gemm_hWhh<<<g3, 256>>>(Whh + (size_t)l * 3 * DD * DD, bhh + (size_t)l * 3 * DD, n_nodes);
        gru_kernel<<<(nh + 255) / 256, 256>>>(n_nodes);
    }

    zero_pool_kernel<<<(NGRAPHS * DD + 255) / 256, 256>>>();
    pool_kernel<<<(nh + 255) / 256, 256>>>(batch, n_nodes);
    readout_kernel<<<NGRAPHS, DD>>>(fc1w, fc1b, fc2w, fc2b);
    lsm_kernel<<<NCLASSES, NGRAPHS>>>(out);
}

// round 7
// speedup vs baseline: 1.1651x; 1.1651x over previous
#include <cuda_runtime.h>
#include <math.h>
#include <stdint.h>

#define NNODES 50000
#define NEDGES 600000
#define DD 128
#define NGRAPHS 512
#define NCLASSES 10
#define NLAYERS 4

// ---------------- scratch (static device globals) ---------------------------
__device__ float d_h[NNODES * DD];
__device__ float d_m[NNODES * DD];
__device__ float d_agg[NNODES * DD];
__device__ float d_gi[NNODES * 3 * DD];
__device__ float d_gh[NNODES * 3 * DD];
__device__ float d_wB1[NLAYERS * 512 * DD];   // [Whh(384) ; Ws^T(128)] per layer
__device__ int   d_off[NNODES + 1];
__device__ int   d_cnt[NNODES];
__device__ int   d_csc[NEDGES];
__device__ float d_pool[NGRAPHS * DD];
__device__ float d_gcnt[NGRAPHS];
__device__ float d_logits[NGRAPHS * NCLASSES];
__device__ int   d_is64;

// ---------------- tf32 helpers ------------------------------------------------
__device__ __forceinline__ uint32_t f2tf32(float x) {
    uint32_t r;
    asm("cvt.rna.tf32.f32 %0, %1;" : "=r"(r) : "f"(x));
    return r;
}
__device__ __forceinline__ void split_tf32(float x, uint32_t& hi, uint32_t& lo) {
    hi = f2tf32(x);
    lo = f2tf32(x - __uint_as_float(hi));
}
__device__ __forceinline__ void mma_tf32(float* c, const uint32_t* a, const uint32_t* b) {
    asm volatile(
        "mma.sync.aligned.m16n8k8.row.col.f32.tf32.tf32.f32 "
        "{%0,%1,%2,%3},{%4,%5,%6,%7},{%8,%9},{%0,%1,%2,%3};"
        : "+f"(c[0]), "+f"(c[1]), "+f"(c[2]), "+f"(c[3])
        : "r"(a[0]), "r"(a[1]), "r"(a[2]), "r"(a[3]), "r"(b[0]), "r"(b[1]));
}

// ---------------- index dtype detection ---------------------------------------
__global__ void detect_kernel(const void* __restrict__ ei) {
    __shared__ int nz;
    if (threadIdx.x == 0) nz = 0;
    __syncthreads();
    const int* w = (const int*)ei;
    int v = w[2 * threadIdx.x + 1];
    if (v != 0) atomicAdd(&nz, 1);
    __syncthreads();
    if (threadIdx.x == 0) d_is64 = (nz == 0) ? 1 : 0;
}
__device__ __forceinline__ int load_idx(const void* p, int i) {
    return d_is64 ? (int)((const long long*)p)[i] : ((const int*)p)[i];
}

// ---------------- utility kernels ---------------------------------------------
__global__ void copy_h_kernel(const float* __restrict__ src, int n) {
    int i = blockIdx.x * blockDim.x + threadIdx.x;
    if (i < n) d_h[i] = src[i];
}
__global__ void zero_cnt_kernel(int n) {
    int i = blockIdx.x * blockDim.x + threadIdx.x;
    if (i < n) d_cnt[i] = 0;
}
__global__ void zero_pool_kernel() {
    int i = blockIdx.x * blockDim.x + threadIdx.x;
    if (i < NGRAPHS * DD) d_pool[i] = 0.f;
    if (i < NGRAPHS) d_gcnt[i] = 0.f;
}
// combined B1 = [Whh (rows 0..383) ; Ws^T (rows 384..511)] per layer, fp32
__global__ void conv_wB1_kernel(const float* __restrict__ Whh, const float* __restrict__ Ws) {
    int i = blockIdx.x * blockDim.x + threadIdx.x;
    if (i >= NLAYERS * 512 * DD) return;
    int l = i / (512 * DD);
    int r = (i / DD) % 512;
    int k = i % DD;
    d_wB1[i] = (r < 384) ? Whh[(size_t)l * 384 * DD + r * DD + k]
                         : Ws[(size_t)l * DD * DD + k * DD + (r - 384)];
}

// ---------------- CSC build ----------------------------------------------------
__global__ void count_kernel(const void* __restrict__ ei, int n_edges) {
    int e = blockIdx.x * blockDim.x + threadIdx.x;
    if (e >= n_edges) return;
    int dst = load_idx(ei, n_edges + e);
    if (dst >= 0 && dst < NNODES) atomicAdd(&d_cnt[dst], 1);
}
__global__ void scan_kernel(int n) {
    __shared__ int tmp[1024];
    __shared__ int carry;
    int tid = threadIdx.x;
    if (tid == 0) carry = 0;
    __syncthreads();
    for (int base = 0; base < n; base += 1024) {
        int v = (base + tid < n) ? d_cnt[base + tid] : 0;
        tmp[tid] = v;
        __syncthreads();
        for (int off = 1; off < 1024; off <<= 1) {
            int t = (tid >= off) ? tmp[tid - off] : 0;
            __syncthreads();
            tmp[tid] += t;
            __syncthreads();
        }
        int excl = tmp[tid] - v;
        if (base + tid < n) d_off[base + tid] = carry + excl;
        __syncthreads();
        if (tid == 1023) carry += tmp[1023];
        __syncthreads();
    }
    if (tid == 0) d_off[n] = carry;
}
__global__ void fill_kernel(const void* __restrict__ ei, int n_edges) {
    int e = blockIdx.x * blockDim.x + threadIdx.x;
    if (e >= n_edges) return;
    int dst = load_idx(ei, n_edges + e);
    int src = load_idx(ei, e);
    if (dst < 0 || dst >= NNODES || src < 0 || src >= NNODES) return;
    int pos = d_off[dst] + atomicAdd(&d_cnt[dst], 1);
    if (pos < NEDGES) d_csc[pos] = src;
}

// ---------------- aggregation: one warp per node, float4 per lane --------------
__global__ void agg_kernel(int n_nodes) {
    int warp = (blockIdx.x * blockDim.x + threadIdx.x) >> 5;
    int lane = threadIdx.x & 31;
    if (warp >= n_nodes) return;
    int s = d_off[warp], e = d_off[warp + 1];
    float4 acc = make_float4(0.f, 0.f, 0.f, 0.f);
    for (int i = s; i < e; i++) {
        int src = d_csc[i];
        float4 v = *(const float4*)(d_m + (size_t)src * DD + lane * 4);
        acc.x += v.x; acc.y += v.y; acc.z += v.z; acc.w += v.w;
    }
    *(float4*)(d_agg + (size_t)warp * DD + lane * 4) = acc;
}

// ---------------- tf32x3 tensor-core GEMM --------------------------------------
// C[M,:] = A[M,128] @ B[N,128]^T (+bias); cols < N1 -> C1 (stride N1), else C2 (stride 128).
// Split-tf32: a = ahi+alo, b = bhi+blo; C += ahi*bhi + ahi*blo + alo*bhi (drop lo*lo ~2^-24).
#define SAW 36
__device__ __forceinline__ void gemm_tf32_body(
    const float* __restrict__ A, const float* __restrict__ B,
    const float* __restrict__ bias, float* __restrict__ C1, int N1,
    float* __restrict__ C2, int M)
{
    __shared__ float sA[128][SAW];
    __shared__ float sB[64][SAW];
    int tid = threadIdx.x, lane = tid & 31, wid = tid >> 5;
    int g = lane >> 2, tg = lane & 3;
    int m0 = blockIdx.x * 128, n0 = blockIdx.y * 64;
    int wm0 = (wid & 3) * 32, wn0 = (wid >> 2) * 32;

    float c[2][4][4] = {};

    for (int k0 = 0; k0 < 128; k0 += 32) {
        // stage A chunk: 128 rows x 32 floats (1024 float4, 4 per thread)
#pragma unroll
        for (int t = 0; t < 4; t++) {
            int ch = tid + t * 256;
            int row = ch >> 3, q = ch & 7;
            float4 v = make_float4(0.f, 0.f, 0.f, 0.f);
            int gr = m0 + row;
            if (gr < M) v = *(const float4*)&A[(size_t)gr * 128 + k0 + q * 4];
            *(float4*)&sA[row][q * 4] = v;
        }
        // stage B chunk: 64 rows x 32 floats (512 float4, 2 per thread)
#pragma unroll
        for (int t = 0; t < 2; t++) {
            int ch = tid + t * 256;
            int row = ch >> 3, q = ch & 7;
            *(float4*)&sB[row][q * 4] = *(const float4*)&B[(size_t)(n0 + row) * 128 + k0 + q * 4];
        }
        __syncthreads();

#pragma unroll
        for (int ks = 0; ks < 32; ks += 8) {
            // PTX m16n8k8 tf32 fragment layout:
            //  a0=A[g][tg] a1=A[g+8][tg] a2=A[g][tg+4] a3=A[g+8][tg+4]
            //  b0=B[tg][g] b1=B[tg+4][g]  (B stored [n][k] -> sB[n][k])
            uint32_t ahi[2][4], alo[2][4], bhi[4][2], blo[4][2];
#pragma unroll
            for (int mt = 0; mt < 2; mt++) {
                int r0 = wm0 + mt * 16 + g;
                split_tf32(sA[r0][ks + tg],         ahi[mt][0], alo[mt][0]);
                split_tf32(sA[r0 + 8][ks + tg],     ahi[mt][1], alo[mt][1]);
                split_tf32(sA[r0][ks + tg + 4],     ahi[mt][2], alo[mt][2]);
                split_tf32(sA[r0 + 8][ks + tg + 4], ahi[mt][3], alo[mt][3]);
            }
#pragma unroll
            for (int nt = 0; nt < 4; nt++) {
                int r = wn0 + nt * 8 + g;
                split_tf32(sB[r][ks + tg],     bhi[nt][0], blo[nt][0]);
                split_tf32(sB[r][ks + tg + 4], bhi[nt][1], blo[nt][1]);
            }
#pragma unroll
            for (int mt = 0; mt < 2; mt++)
#pragma unroll
                for (int nt = 0; nt < 4; nt++) {
                    mma_tf32(c[mt][nt], ahi[mt], bhi[nt]);
                    mma_tf32(c[mt][nt], ahi[mt], blo[nt]);
                    mma_tf32(c[mt][nt], alo[mt], bhi[nt]);
                }
        }
        __syncthreads();
    }

    // store: c0,c1 at (row=g, col=tg*2,+1), c2,c3 at row g+8
#pragma unroll
    for (int mt = 0; mt < 2; mt++)
#pragma unroll
        for (int nt = 0; nt < 4; nt++)
#pragma unroll
            for (int hr = 0; hr < 2; hr++) {
                int row = m0 + wm0 + mt * 16 + g + hr * 8;
                if (row >= M) continue;
                int col = n0 + wn0 + nt * 8 + tg * 2;
                float v0 = c[mt][nt][hr * 2 + 0];
                float v1 = c[mt][nt][hr * 2 + 1];
                if (col < N1) {
                    if (bias) { v0 += bias[col]; v1 += bias[col + 1]; }
                    *(float2*)&C1[(size_t)row * N1 + col] = make_float2(v0, v1);
                } else {
                    *(float2*)&C2[(size_t)row * DD + (col - N1)] = make_float2(v0, v1);
                }
            }
}

// fused: [gh | m] = h @ [Whh^T | Ws]
__global__ __launch_bounds__(256) void gemm1_kernel(const float* __restrict__ bhh, int l, int M) {
    gemm_tf32_body(d_h, d_wB1 + (size_t)l * 512 * DD, bhh, d_gh, 384, d_m, M);
}
// gi = agg @ Wih^T + bih   (Wih is already [384,128] row-major = B[n][k])
__global__ __launch_bounds__(256) void gemm2_kernel(const float* __restrict__ Wih,
                                                    const float* __restrict__ bih, int M) {
    gemm_tf32_body(d_agg, Wih, bih, d_gi, 384, nullptr, M);
}

// ---------------- fused GRU gates + ReLU ---------------------------------------
__global__ void gru_kernel(int n_nodes) {
    int idx = blockIdx.x * blockDim.x + threadIdx.x;
    if (idx >= n_nodes * DD) return;
    int i = idx / DD, j = idx % DD;
    const float* gir = d_gi + (size_t)i * 3 * DD;
    const float* ghr = d_gh + (size_t)i * 3 * DD;
    float ir = gir[j], iz = gir[DD + j], in_ = gir[2 * DD + j];
    float hr = ghr[j], hz = ghr[DD + j], hn = ghr[2 * DD + j];
    float r = 1.f / (1.f + expf(-(ir + hr)));
    float z = 1.f / (1.f + expf(-(iz + hz)));
    float nn = tanhf(in_ + r * hn);
    float hv = d_h[idx];
    d_h[idx] = fmaxf((1.f - z) * nn + z * hv, 0.f);
}

// ---------------- mean pool -----------------------------------------------------
__global__ void pool_kernel(const void* __restrict__ batch, int n_nodes) {
    int idx = blockIdx.x * blockDim.x + threadIdx.x;
    if (idx >= n_nodes * DD) return;
    int i = idx / DD, j = idx % DD;
    int g = load_idx(batch, i);
    if (g < 0 || g >= NGRAPHS) return;
    atomicAdd(&d_pool[g * DD + j], d_h[idx]);
    if (j == 0) atomicAdd(&d_gcnt[g], 1.f);
}

// ---------------- readout FC1(elu) + FC2 ----------------------------------------
__global__ void readout_kernel(const float* __restrict__ fc1w, const float* __restrict__ fc1b,
                               const float* __restrict__ fc2w, const float* __restrict__ fc2b) {
    int g = blockIdx.x;
    int j = threadIdx.x;
    __shared__ float hg[DD];
    __shared__ float h2[DD];
    float c = fmaxf(d_gcnt[g], 1.f);
    hg[j] = d_pool[g * DD + j] / c;
    __syncthreads();
    float a = fc1b[j];
#pragma unroll 4
    for (int k = 0; k < DD; k++) a += hg[k] * fc1w[j * DD + k];
    h2[j] = (a > 0.f) ? a : expm1f(a);
    __syncthreads();
    if (j < NCLASSES) {
        float s = fc2b[j];
#pragma unroll 4
        for (int k = 0; k < DD; k++) s += h2[k] * fc2w[j * DD + k];
        d_logits[g * NCLASSES + j] = s;
    }
}

// ---------------- log_softmax over axis 0 ---------------------------------------
__global__ void lsm_kernel(float* __restrict__ out) {
    int c = blockIdx.x;
    int g = threadIdx.x;
    __shared__ float sh[NGRAPHS];
    float x = d_logits[g * NCLASSES + c];
    sh[g] = x;
    __syncthreads();
    for (int off = NGRAPHS / 2; off > 0; off >>= 1) {
        if (g < off) sh[g] = fmaxf(sh[g], sh[g + off]);
        __syncthreads();
    }
    float mx = sh[0];
    __syncthreads();
    sh[g] = expf(x - mx);
    __syncthreads();
    for (int off = NGRAPHS / 2; off > 0; off >>= 1) {
        if (g < off) sh[g] += sh[g + off];
        __syncthreads();
    }
    float lse = mx + logf(sh[0]);
    out[g * NCLASSES + c] = x - lse;
}

// ---------------- launch ---------------------------------------------------------
extern "C" void kernel_launch(void* const* d_in, const int* in_sizes, int n_in,
                              void* d_out, int out_size) {
    const float* h_in  = (const float*)d_in[0];
    const void*  ei    = d_in[1];
    const void*  batch = d_in[3];
    const float* Ws   = (const float*)d_in[4];
    const float* Wih  = (const float*)d_in[5];
    const float* Whh  = (const float*)d_in[6];
    const float* bih  = (const float*)d_in[7];
    const float* bhh  = (const float*)d_in[8];
    const float* fc1w = (const float*)d_in[9];
    const float* fc1b = (const float*)d_in[10];
    const float* fc2w = (const float*)d_in[11];
    const float* fc2b = (const float*)d_in[12];
    float* out = (float*)d_out;

    int n_nodes = in_sizes[0] / DD;
    int n_edges = in_sizes[1] / 2;
    int nh = n_nodes * DD;

    detect_kernel<<<1, 128>>>(ei);
    copy_h_kernel<<<(nh + 255) / 256, 256>>>(h_in, nh);
    conv_wB1_kernel<<<(NLAYERS * 512 * DD + 255) / 256, 256>>>(Whh, Ws);

    // CSC build (once; reused across layers)
    zero_cnt_kernel<<<(n_nodes + 255) / 256, 256>>>(n_nodes);
    count_kernel<<<(n_edges + 255) / 256, 256>>>(ei, n_edges);
    scan_kernel<<<1, 1024>>>(n_nodes);
    zero_cnt_kernel<<<(n_nodes + 255) / 256, 256>>>(n_nodes);
    fill_kernel<<<(n_edges + 255) / 256, 256>>>(ei, n_edges);

    dim3 grid1((n_nodes + 127) / 128, 8);   // 512 output cols: [gh(384) | m(128)]
    dim3 grid2((n_nodes + 127) / 128, 6);   // 384 output cols: gi

    for (int l = 0; l < NLAYERS; l++) {
        gemm1_kernel<<<grid1, 256>>>(bhh + (size_t)l * 3 * DD, l, n_nodes);
        agg_kernel<<<(n_nodes * 32 + 255) / 256, 256>>>(n_nodes);
        gemm2_kernel<<<grid2, 256>>>(Wih + (size_t)l * 384 * DD, bih + (size_t)l * 3 * DD, n_nodes);
        gru_kernel<<<(nh + 255) / 256, 256>>>(n_nodes);
    }

    zero_pool_kernel<<<(NGRAPHS * DD + 255) / 256, 256>>>();
    pool_kernel<<<(nh + 255) / 256, 256>>>(batch, n_nodes);
    readout_kernel<<<NGRAPHS, DD>>>(fc1w, fc1b, fc2w, fc2b);
    lsm_kernel<<<NCLASSES, NGRAPHS>>>(out);
}